// round 2
// baseline (speedup 1.0000x reference)
#include <cuda_runtime.h>
#include <math.h>

#define Bb 32
#define NS 4096
#define Dd 256
#define Hh 4
#define Ll 6
#define NQ 512
#define NK 1024
#define DH 64
#define ATTN_SCALE 0.125f

// ---------------- scratch (static device globals; no allocation) -------------
__device__ float g_upd[Bb * NS * Dd];          // working copy of update_tensor
__device__ float g_q[Bb * NQ * Dd];
__device__ float g_k[Bb * NK * Dd];
__device__ float g_Qp[Bb * NQ * Dd];
__device__ float g_Kp[Bb * NK * Dd];
__device__ float g_Vp[Bb * NK * Dd];
__device__ float g_S[(size_t)Bb * Hh * NQ * NK];  // scores / attn (268 MB)
__device__ float g_ctx[Bb * NQ * Dd];
__device__ float g_h[Bb * NQ * Dd];
__device__ float g_t1[Bb * NQ * Dd];
__device__ float g_t2[Bb * NQ * Dd];

// ---------------- helpers ----------------------------------------------------
__device__ __forceinline__ float bsum256(float v) {
    __shared__ float sh[8];
    __syncthreads();                  // protect sh reuse across calls
    int lane = threadIdx.x & 31, w = threadIdx.x >> 5;
#pragma unroll
    for (int o = 16; o; o >>= 1) v += __shfl_xor_sync(0xffffffffu, v, o);
    if (lane == 0) sh[w] = v;
    __syncthreads();
    float r = 0.f;
#pragma unroll
    for (int j = 0; j < 8; j++) r += sh[j];
    return r;
}

__device__ __forceinline__ float bmax256(float v) {
    __shared__ float shm[8];
    __syncthreads();
    int lane = threadIdx.x & 31, w = threadIdx.x >> 5;
#pragma unroll
    for (int o = 16; o; o >>= 1) v = fmaxf(v, __shfl_xor_sync(0xffffffffu, v, o));
    if (lane == 0) shm[w] = v;
    __syncthreads();
    float r = -3.0e38f;
#pragma unroll
    for (int j = 0; j < 8; j++) r = fmaxf(r, shm[j]);
    return r;
}

__device__ __forceinline__ float gelu_tanh(float x) {
    float x3 = x * x * x;
    return 0.5f * x * (1.f + tanhf(0.7978845608028654f * (x + 0.044715f * x3)));
}

// ---------------- utility kernels --------------------------------------------
__global__ void k_zero(float* dst, int n) {
    for (int i = blockIdx.x * blockDim.x + threadIdx.x; i < n; i += gridDim.x * blockDim.x)
        dst[i] = 0.f;
}
__global__ void k_copy(const float* __restrict__ src, float* __restrict__ dst, int n) {
    for (int i = blockIdx.x * blockDim.x + threadIdx.x; i < n; i += gridDim.x * blockDim.x)
        dst[i] = src[i];
}

// ---------------- gather + layernorm (row = one (b, i)) ----------------------
// out[b*NR+i, :] = LN(emb[idx[i]] + upd[b, idx[i]], s, b), 256 threads/row
__global__ void k_gather_ln(const float* __restrict__ emb, const float* __restrict__ upd,
                            const int* __restrict__ idx, const float* __restrict__ sc,
                            const float* __restrict__ bi, float* __restrict__ out, int NR) {
    int row = blockIdx.x;
    int b = row / NR, i = row - b * NR;
    int t = threadIdx.x;
    int id = idx[i];
    float x = emb[id * Dd + t] + upd[((size_t)b * NS + id) * Dd + t];
    float m = bsum256(x) * (1.f / 256.f);
    float dv = x - m;
    float var = bsum256(dv * dv) * (1.f / 256.f);
    out[(size_t)row * Dd + t] = dv * rsqrtf(var + 1e-5f) * sc[t] + bi[t];
}

// ---------------- plain layernorm on rows of 256 ------------------------------
__global__ void k_ln(const float* __restrict__ x, const float* __restrict__ sc,
                     const float* __restrict__ bi, float* __restrict__ out) {
    size_t row = blockIdx.x;
    int t = threadIdx.x;
    float v = x[row * Dd + t];
    float m = bsum256(v) * (1.f / 256.f);
    float dv = v - m;
    float var = bsum256(dv * dv) * (1.f / 256.f);
    out[row * Dd + t] = dv * rsqrtf(var + 1e-5f) * sc[t] + bi[t];
}

// res = LN(LN(h+f, os, ob), es, eb)
__global__ void k_dln(const float* __restrict__ hb, const float* __restrict__ f,
                      const float* __restrict__ os, const float* __restrict__ ob,
                      const float* __restrict__ es, const float* __restrict__ eb,
                      float* __restrict__ res) {
    size_t row = blockIdx.x;
    int t = threadIdx.x;
    float x = hb[row * Dd + t] + f[row * Dd + t];
    float m = bsum256(x) * (1.f / 256.f);
    float dv = x - m;
    float var = bsum256(dv * dv) * (1.f / 256.f);
    float y = dv * rsqrtf(var + 1e-5f) * os[t] + ob[t];
    m = bsum256(y) * (1.f / 256.f);
    dv = y - m;
    var = bsum256(dv * dv) * (1.f / 256.f);
    res[row * Dd + t] = dv * rsqrtf(var + 1e-5f) * es[t] + eb[t];
}

// ---------------- GEMM: C[M,256] = act(A[M,256] @ W[256,256] + bias) ----------
// 64x64 block tile, 4x4 thread tile, TK=16, 256 threads
template <int ACT>
__global__ void gemm256(const float* __restrict__ A, const float* __restrict__ W,
                        const float* __restrict__ bias, float* __restrict__ C) {
    __shared__ float As[16][65];   // [k][m]
    __shared__ float Ws[16][65];   // [k][n]
    int m0 = blockIdx.x * 64;
    int n0 = blockIdx.y * 64;
    int tid = threadIdx.x;
    int ty = tid >> 4, tx = tid & 15;
    float acc[4][4] = {};
    for (int kc = 0; kc < 16; kc++) {
        int kbase = kc * 16;
#pragma unroll
        for (int i = tid; i < 1024; i += 256) {
            int r = i >> 4, c = i & 15;                 // r: m (0..63), c: k (0..15)
            As[c][r] = A[(size_t)(m0 + r) * Dd + kbase + c];
        }
#pragma unroll
        for (int i = tid; i < 1024; i += 256) {
            int r = i >> 6, c = i & 63;                 // r: k (0..15), c: n (0..63)
            Ws[r][c] = W[(size_t)(kbase + r) * Dd + n0 + c];
        }
        __syncthreads();
#pragma unroll
        for (int k = 0; k < 16; k++) {
            float a[4], w[4];
#pragma unroll
            for (int i = 0; i < 4; i++) a[i] = As[k][ty * 4 + i];
#pragma unroll
            for (int j = 0; j < 4; j++) w[j] = Ws[k][tx * 4 + j];
#pragma unroll
            for (int i = 0; i < 4; i++)
#pragma unroll
                for (int j = 0; j < 4; j++) acc[i][j] += a[i] * w[j];
        }
        __syncthreads();
    }
#pragma unroll
    for (int j = 0; j < 4; j++) {
        float bj = bias ? bias[n0 + tx * 4 + j] : 0.f;
#pragma unroll
        for (int i = 0; i < 4; i++) {
            float v = acc[i][j] + bj;
            if (ACT == 1) v = gelu_tanh(v);
            C[(size_t)(m0 + ty * 4 + i) * Dd + n0 + tx * 4 + j] = v;
        }
    }
}

// ---------------- attention scores: S[b,h,q,k] = mask? Q·K*scale : -1e9 ------
// grid (NQ/64, NK/64, B*H)
__global__ void k_scores(const float* __restrict__ Q, const float* __restrict__ K,
                         const float* __restrict__ mask, float* __restrict__ S) {
    __shared__ float Qs[64][65];
    __shared__ float Ks[64][65];
    int q0 = blockIdx.x * 64;
    int k0 = blockIdx.y * 64;
    int bh = blockIdx.z;
    int b = bh / Hh, h = bh - b * Hh;
    int tid = threadIdx.x;
#pragma unroll
    for (int i = tid; i < 4096; i += 256) {
        int r = i >> 6, c = i & 63;
        Qs[r][c] = Q[(size_t)(b * NQ + q0 + r) * Dd + h * DH + c];
        Ks[r][c] = K[(size_t)(b * NK + k0 + r) * Dd + h * DH + c];
    }
    __syncthreads();
    int ty = tid >> 4, tx = tid & 15;
    float acc[4][4] = {};
#pragma unroll 8
    for (int d = 0; d < 64; d++) {
        float a[4], kk[4];
#pragma unroll
        for (int i = 0; i < 4; i++) a[i] = Qs[ty * 4 + i][d];
#pragma unroll
        for (int j = 0; j < 4; j++) kk[j] = Ks[tx * 4 + j][d];
#pragma unroll
        for (int i = 0; i < 4; i++)
#pragma unroll
            for (int j = 0; j < 4; j++) acc[i][j] += a[i] * kk[j];
    }
#pragma unroll
    for (int i = 0; i < 4; i++) {
        int q = q0 + ty * 4 + i;
#pragma unroll
        for (int j = 0; j < 4; j++) {
            int k = k0 + tx * 4 + j;
            float mv = mask[(size_t)q * NK + k];
            S[((size_t)bh * NQ + q) * NK + k] =
                (mv > 0.5f) ? acc[i][j] * ATTN_SCALE : -1e9f;
        }
    }
}

// ---------------- softmax over rows of 1024 -----------------------------------
__global__ void k_softmax(float* __restrict__ S) {
    size_t row = blockIdx.x;
    float* p = S + row * NK;
    int t = threadIdx.x;
    float v[4];
    float mx = -3.0e38f;
#pragma unroll
    for (int j = 0; j < 4; j++) { v[j] = p[t + j * 256]; mx = fmaxf(mx, v[j]); }
    mx = bmax256(mx);
    float s = 0.f;
#pragma unroll
    for (int j = 0; j < 4; j++) { v[j] = __expf(v[j] - mx); s += v[j]; }
    s = bsum256(s);
    float inv = 1.f / s;
#pragma unroll
    for (int j = 0; j < 4; j++) p[t + j * 256] = v[j] * inv;
}

// ---------------- ctx[b,q,h*64+d] = sum_k attn[b,h,q,k] * V[b,k,h*64+d] ------
// grid (NQ/64, 1, B*H)
__global__ void k_ctx(const float* __restrict__ S, const float* __restrict__ V,
                      float* __restrict__ ctx) {
    __shared__ float As[16][65];   // [k][q]
    __shared__ float Vs[16][65];   // [k][d]
    int q0 = blockIdx.x * 64;
    int bh = blockIdx.z;
    int b = bh / Hh, h = bh - b * Hh;
    int tid = threadIdx.x;
    int ty = tid >> 4, tx = tid & 15;
    float acc[4][4] = {};
    for (int kc = 0; kc < 64; kc++) {
        int kb = kc * 16;
#pragma unroll
        for (int i = tid; i < 1024; i += 256) {
            int r = i >> 4, c = i & 15;               // r: q, c: k
            As[c][r] = S[((size_t)bh * NQ + q0 + r) * NK + kb + c];
        }
#pragma unroll
        for (int i = tid; i < 1024; i += 256) {
            int r = i >> 6, c = i & 63;               // r: k, c: d
            Vs[r][c] = V[(size_t)(b * NK + kb + r) * Dd + h * DH + c];
        }
        __syncthreads();
#pragma unroll
        for (int k = 0; k < 16; k++) {
            float a[4], vv[4];
#pragma unroll
            for (int i = 0; i < 4; i++) a[i] = As[k][ty * 4 + i];
#pragma unroll
            for (int j = 0; j < 4; j++) vv[j] = Vs[k][tx * 4 + j];
#pragma unroll
            for (int i = 0; i < 4; i++)
#pragma unroll
                for (int j = 0; j < 4; j++) acc[i][j] += a[i] * vv[j];
        }
        __syncthreads();
    }
#pragma unroll
    for (int i = 0; i < 4; i++)
#pragma unroll
        for (int j = 0; j < 4; j++)
            ctx[(size_t)(b * NQ + q0 + ty * 4 + i) * Dd + h * DH + tx * 4 + j] = acc[i][j];
}

// ---------------- scatter-add (atomics handle duplicate indices) -------------
__global__ void k_scatter(const float* __restrict__ res, const int* __restrict__ qi,
                          float* __restrict__ upd, float* __restrict__ out) {
    int n = Bb * NQ * Dd;
    for (int i = blockIdx.x * blockDim.x + threadIdx.x; i < n; i += gridDim.x * blockDim.x) {
        int b = i / (NQ * Dd);
        int rem = i - b * (NQ * Dd);
        int q = rem >> 8;          // / 256
        int d = rem & 255;
        int id = qi[q];
        float v = res[i];
        size_t o = ((size_t)b * NS + id) * Dd + d;
        atomicAdd(&upd[o], v);
        atomicAdd(&out[o], v);
    }
}

// ---------------- launch ------------------------------------------------------
extern "C" void kernel_launch(void* const* d_in, const int* in_sizes, int n_in,
                              void* d_out, int out_size) {
    const float* upd_in = (const float*)d_in[0];
    const float* emb    = (const float*)d_in[1];
    const float* mask   = (const float*)d_in[2];
    const float* Wq     = (const float*)d_in[3];
    const float* Wk     = (const float*)d_in[4];
    const float* Wv     = (const float*)d_in[5];
    const float* Wo     = (const float*)d_in[6];
    const float* W1     = (const float*)d_in[7];
    const float* b1     = (const float*)d_in[8];
    const float* W2     = (const float*)d_in[9];
    const float* b2     = (const float*)d_in[10];
    const float* sys_s  = (const float*)d_in[11];
    const float* sys_b  = (const float*)d_in[12];
    const float* eff_s  = (const float*)d_in[13];
    const float* eff_b  = (const float*)d_in[14];
    const float* in_s   = (const float*)d_in[15];
    const float* in_b   = (const float*)d_in[16];
    const float* out_s  = (const float*)d_in[17];
    const float* out_b  = (const float*)d_in[18];
    const int*   qidx   = (const int*)d_in[19];
    const int*   kidx   = (const int*)d_in[20];
    float* out = (float*)d_out;

    float *upd, *qb, *kb, *Qp, *Kp, *Vp, *S, *ctx, *hb, *t1, *t2;
    cudaGetSymbolAddress((void**)&upd, g_upd);
    cudaGetSymbolAddress((void**)&qb,  g_q);
    cudaGetSymbolAddress((void**)&kb,  g_k);
    cudaGetSymbolAddress((void**)&Qp,  g_Qp);
    cudaGetSymbolAddress((void**)&Kp,  g_Kp);
    cudaGetSymbolAddress((void**)&Vp,  g_Vp);
    cudaGetSymbolAddress((void**)&S,   g_S);
    cudaGetSymbolAddress((void**)&ctx, g_ctx);
    cudaGetSymbolAddress((void**)&hb,  g_h);
    cudaGetSymbolAddress((void**)&t1,  g_t1);
    cudaGetSymbolAddress((void**)&t2,  g_t2);

    int n_upd = Bb * NS * Dd;
    k_zero<<<8192, 256>>>(out, n_upd);
    k_copy<<<8192, 256>>>(upd_in, upd, n_upd);

    for (int l = 0; l < Ll; l++) {
        const float* mask_l = mask + (size_t)l * NQ * NK;
        const int* qi = qidx + l * NQ;
        const int* ki = kidx + l * NK;

        k_gather_ln<<<Bb * NQ, 256>>>(emb, upd, qi, sys_s, sys_b, qb, NQ);
        k_gather_ln<<<Bb * NK, 256>>>(emb, upd, ki, sys_s, sys_b, kb, NK);

        gemm256<0><<<dim3(Bb * NQ / 64, 4), 256>>>(qb, Wq, nullptr, Qp);
        gemm256<0><<<dim3(Bb * NK / 64, 4), 256>>>(kb, Wk, nullptr, Kp);
        gemm256<0><<<dim3(Bb * NK / 64, 4), 256>>>(kb, Wv, nullptr, Vp);

        k_scores<<<dim3(NQ / 64, NK / 64, Bb * Hh), 256>>>(Qp, Kp, mask_l, S);
        k_softmax<<<Bb * Hh * NQ, 256>>>(S);
        k_ctx<<<dim3(NQ / 64, 1, Bb * Hh), 256>>>(S, Vp, ctx);

        gemm256<0><<<dim3(Bb * NQ / 64, 4), 256>>>(ctx, Wo, nullptr, t1);
        k_ln<<<Bb * NQ, 256>>>(t1, in_s, in_b, hb);

        gemm256<1><<<dim3(Bb * NQ / 64, 4), 256>>>(hb, W1, b1, t1);
        gemm256<0><<<dim3(Bb * NQ / 64, 4), 256>>>(t1, W2, b2, t2);

        k_dln<<<Bb * NQ, 256>>>(hb, t2, out_s, out_b, eff_s, eff_b, ctx);
        k_scatter<<<8192, 256>>>(ctx, qi, upd, out);
    }
}

// round 3
// speedup vs baseline: 2.9134x; 2.9134x over previous
#include <cuda_runtime.h>
#include <math.h>

#define Bb 32
#define NS 4096
#define Dd 256
#define Hh 4
#define Ll 6
#define NQ 512
#define NK 1024
#define DH 64
#define ATTN_SCALE 0.125f

// ---------------- scratch (static device globals; no allocation) -------------
__device__ float g_upd[Bb * NS * Dd];
__device__ float g_q[Bb * NQ * Dd];
__device__ float g_k[Bb * NK * Dd];
__device__ float g_Qp[Bb * NQ * Dd];
__device__ float g_Kp[Bb * NK * Dd];
__device__ float g_Vp[Bb * NK * Dd];
__device__ float g_ctx[Bb * NQ * Dd];
__device__ float g_h[Bb * NQ * Dd];
__device__ float g_t1[Bb * NQ * Dd];
__device__ float g_t2[Bb * NQ * Dd];

// ---------------- helpers ----------------------------------------------------
__device__ __forceinline__ float bsum256(float v) {
    __shared__ float sh[8];
    __syncthreads();
    int lane = threadIdx.x & 31, w = threadIdx.x >> 5;
#pragma unroll
    for (int o = 16; o; o >>= 1) v += __shfl_xor_sync(0xffffffffu, v, o);
    if (lane == 0) sh[w] = v;
    __syncthreads();
    float r = 0.f;
#pragma unroll
    for (int j = 0; j < 8; j++) r += sh[j];
    return r;
}

__device__ __forceinline__ float gelu_tanh(float x) {
    float x3 = x * x * x;
    return 0.5f * x * (1.f + tanhf(0.7978845608028654f * (x + 0.044715f * x3)));
}

__device__ __forceinline__ unsigned f2tf(float x) {
    unsigned r;
    asm("cvt.rna.tf32.f32 %0, %1;" : "=r"(r) : "f"(x));
    return r;
}

__device__ __forceinline__ void mma_tf32(float c[4], unsigned a0, unsigned a1,
                                         unsigned a2, unsigned a3,
                                         unsigned b0, unsigned b1) {
    asm volatile(
        "mma.sync.aligned.m16n8k8.row.col.f32.tf32.tf32.f32 "
        "{%0,%1,%2,%3}, {%4,%5,%6,%7}, {%8,%9}, {%0,%1,%2,%3};"
        : "+f"(c[0]), "+f"(c[1]), "+f"(c[2]), "+f"(c[3])
        : "r"(a0), "r"(a1), "r"(a2), "r"(a3), "r"(b0), "r"(b1));
}

// ---------------- utility kernels --------------------------------------------
__global__ void k_zero(float* dst, int n) {
    for (int i = blockIdx.x * blockDim.x + threadIdx.x; i < n; i += gridDim.x * blockDim.x)
        dst[i] = 0.f;
}
__global__ void k_copy(const float* __restrict__ src, float* __restrict__ dst, int n) {
    for (int i = blockIdx.x * blockDim.x + threadIdx.x; i < n; i += gridDim.x * blockDim.x)
        dst[i] = src[i];
}

// ---------------- gather + layernorm -----------------------------------------
__global__ void k_gather_ln(const float* __restrict__ emb, const float* __restrict__ upd,
                            const int* __restrict__ idx, const float* __restrict__ sc,
                            const float* __restrict__ bi, float* __restrict__ out, int NR) {
    int row = blockIdx.x;
    int b = row / NR, i = row - b * NR;
    int t = threadIdx.x;
    int id = idx[i];
    float x = emb[id * Dd + t] + upd[((size_t)b * NS + id) * Dd + t];
    float m = bsum256(x) * (1.f / 256.f);
    float dv = x - m;
    float var = bsum256(dv * dv) * (1.f / 256.f);
    out[(size_t)row * Dd + t] = dv * rsqrtf(var + 1e-5f) * sc[t] + bi[t];
}

__global__ void k_ln(const float* __restrict__ x, const float* __restrict__ sc,
                     const float* __restrict__ bi, float* __restrict__ out) {
    size_t row = blockIdx.x;
    int t = threadIdx.x;
    float v = x[row * Dd + t];
    float m = bsum256(v) * (1.f / 256.f);
    float dv = v - m;
    float var = bsum256(dv * dv) * (1.f / 256.f);
    out[row * Dd + t] = dv * rsqrtf(var + 1e-5f) * sc[t] + bi[t];
}

__global__ void k_dln(const float* __restrict__ hb, const float* __restrict__ f,
                      const float* __restrict__ os, const float* __restrict__ ob,
                      const float* __restrict__ es, const float* __restrict__ eb,
                      float* __restrict__ res) {
    size_t row = blockIdx.x;
    int t = threadIdx.x;
    float x = hb[row * Dd + t] + f[row * Dd + t];
    float m = bsum256(x) * (1.f / 256.f);
    float dv = x - m;
    float var = bsum256(dv * dv) * (1.f / 256.f);
    float y = dv * rsqrtf(var + 1e-5f) * os[t] + ob[t];
    m = bsum256(y) * (1.f / 256.f);
    dv = y - m;
    var = bsum256(dv * dv) * (1.f / 256.f);
    res[row * Dd + t] = dv * rsqrtf(var + 1e-5f) * es[t] + eb[t];
}

// ---------------- tf32 MMA GEMM: C[M,256] = act(A @ W + bias) -----------------
// Block tile 128(M)x64(N), 8 warps (warp = m16 strip x n64), K chunk 32.
template <int ACT>
__global__ void proj_mma(const float* __restrict__ A, const float* __restrict__ W,
                         const float* __restrict__ bias, float* __restrict__ C) {
    __shared__ float As[128][36];  // stride 36 -> conflict-free frag loads
    __shared__ float Ws[32][72];   // stride 72 -> conflict-free frag loads
    int m0 = blockIdx.x * 128, n0 = blockIdx.y * 64;
    int tid = threadIdx.x, warp = tid >> 5, lane = tid & 31;
    int g = lane >> 2, tg = lane & 3;
    int mw = warp * 16;
    float acc[8][4];
#pragma unroll
    for (int j = 0; j < 8; j++)
#pragma unroll
        for (int i = 0; i < 4; i++) acc[j][i] = 0.f;

    for (int kc = 0; kc < 256; kc += 32) {
        __syncthreads();
#pragma unroll
        for (int i = tid; i < 1024; i += 256) {
            int r = i >> 3, c = (i & 7) << 2;
            float4 v = *(const float4*)&A[(size_t)(m0 + r) * Dd + kc + c];
            As[r][c] = v.x; As[r][c + 1] = v.y; As[r][c + 2] = v.z; As[r][c + 3] = v.w;
        }
#pragma unroll
        for (int i = tid; i < 512; i += 256) {
            int r = i >> 4, c = (i & 15) << 2;
            float4 v = *(const float4*)&W[(size_t)(kc + r) * Dd + n0 + c];
            Ws[r][c] = v.x; Ws[r][c + 1] = v.y; Ws[r][c + 2] = v.z; Ws[r][c + 3] = v.w;
        }
        __syncthreads();
#pragma unroll
        for (int k8 = 0; k8 < 4; k8++) {
            int kk = k8 * 8;
            unsigned a0 = f2tf(As[mw + g][kk + tg]);
            unsigned a1 = f2tf(As[mw + g + 8][kk + tg]);
            unsigned a2 = f2tf(As[mw + g][kk + tg + 4]);
            unsigned a3 = f2tf(As[mw + g + 8][kk + tg + 4]);
#pragma unroll
            for (int j = 0; j < 8; j++) {
                unsigned b0 = f2tf(Ws[kk + tg][j * 8 + g]);
                unsigned b1 = f2tf(Ws[kk + tg + 4][j * 8 + g]);
                mma_tf32(acc[j], a0, a1, a2, a3, b0, b1);
            }
        }
    }
#pragma unroll
    for (int j = 0; j < 8; j++) {
        int col = n0 + j * 8 + 2 * tg;
        float bv0 = bias ? bias[col] : 0.f;
        float bv1 = bias ? bias[col + 1] : 0.f;
        float v0 = acc[j][0] + bv0, v1 = acc[j][1] + bv1;
        float v2 = acc[j][2] + bv0, v3 = acc[j][3] + bv1;
        if (ACT) { v0 = gelu_tanh(v0); v1 = gelu_tanh(v1); v2 = gelu_tanh(v2); v3 = gelu_tanh(v3); }
        int r0 = m0 + mw + g;
        *(float2*)&C[(size_t)r0 * Dd + col] = make_float2(v0, v1);
        *(float2*)&C[(size_t)(r0 + 8) * Dd + col] = make_float2(v2, v3);
    }
}

// ---------------- fused flash attention (tf32 MMA, online softmax) ------------
// grid (NQ/128, 1, B*H); block 256 (8 warps, each warp owns a 16-row q strip)
__global__ void flash_attn(const float* __restrict__ Q, const float* __restrict__ K,
                           const float* __restrict__ V, const float* __restrict__ mask,
                           float* __restrict__ ctx) {
    extern __shared__ float sm[];
    float(*Qs)[68] = (float(*)[68])sm;                // 128 x 68
    float(*Ks)[68] = (float(*)[68])(sm + 8704);       // 64 x 68
    float(*Vs)[72] = (float(*)[72])(sm + 13056);      // 64 x 72
    float(*Ps)[68] = (float(*)[68])(sm + 17664);      // 128 x 68

    int bh = blockIdx.z;
    int b = bh >> 2, h = bh & 3;
    int q0 = blockIdx.x * 128;
    int tid = threadIdx.x, warp = tid >> 5, lane = tid & 31;
    int g = lane >> 2, tg = lane & 3;
    int mw = warp * 16;

    const float* Qg = Q + ((size_t)(b * NQ + q0)) * Dd + h * DH;
    const float* Kg = K + ((size_t)b * NK) * Dd + h * DH;
    const float* Vg = V + ((size_t)b * NK) * Dd + h * DH;

#pragma unroll
    for (int i = tid; i < 2048; i += 256) {
        int r = i >> 4, c = (i & 15) << 2;
        float4 v = *(const float4*)&Qg[(size_t)r * Dd + c];
        Qs[r][c] = v.x; Qs[r][c + 1] = v.y; Qs[r][c + 2] = v.z; Qs[r][c + 3] = v.w;
    }

    float O[8][4];
#pragma unroll
    for (int j = 0; j < 8; j++)
#pragma unroll
        for (int i = 0; i < 4; i++) O[j][i] = 0.f;
    float m0r = -3.0e38f, m1r = -3.0e38f, l0 = 0.f, l1 = 0.f;

    const float* mrow0 = mask + (size_t)(q0 + mw + g) * NK;
    const float* mrow1 = mask + (size_t)(q0 + mw + g + 8) * NK;

    for (int kt = 0; kt < 16; kt++) {
        __syncthreads();  // previous iter done with Ks/Vs
        int kbase = kt * 64;
#pragma unroll
        for (int i = tid; i < 1024; i += 256) {
            int r = i >> 4, c = (i & 15) << 2;
            float4 kv = *(const float4*)&Kg[(size_t)(kbase + r) * Dd + c];
            Ks[r][c] = kv.x; Ks[r][c + 1] = kv.y; Ks[r][c + 2] = kv.z; Ks[r][c + 3] = kv.w;
            float4 vv = *(const float4*)&Vg[(size_t)(kbase + r) * Dd + c];
            Vs[r][c] = vv.x; Vs[r][c + 1] = vv.y; Vs[r][c + 2] = vv.z; Vs[r][c + 3] = vv.w;
        }
        __syncthreads();

        // S = Q @ K^T
        float s[8][4];
#pragma unroll
        for (int j = 0; j < 8; j++)
#pragma unroll
            for (int i = 0; i < 4; i++) s[j][i] = 0.f;
#pragma unroll
        for (int k8 = 0; k8 < 8; k8++) {
            int kk = k8 * 8;
            unsigned a0 = f2tf(Qs[mw + g][kk + tg]);
            unsigned a1 = f2tf(Qs[mw + g + 8][kk + tg]);
            unsigned a2 = f2tf(Qs[mw + g][kk + tg + 4]);
            unsigned a3 = f2tf(Qs[mw + g + 8][kk + tg + 4]);
#pragma unroll
            for (int j = 0; j < 8; j++) {
                unsigned b0 = f2tf(Ks[j * 8 + g][kk + tg]);
                unsigned b1 = f2tf(Ks[j * 8 + g][kk + tg + 4]);
                mma_tf32(s[j], a0, a1, a2, a3, b0, b1);
            }
        }

        // scale + mask + row max
        float mx0 = -3.0e38f, mx1 = -3.0e38f;
#pragma unroll
        for (int j = 0; j < 8; j++) {
            int col = kbase + j * 8 + 2 * tg;
            float2 mk0 = *(const float2*)&mrow0[col];
            float2 mk1 = *(const float2*)&mrow1[col];
            s[j][0] = (mk0.x > 0.5f) ? s[j][0] * ATTN_SCALE : -1e9f;
            s[j][1] = (mk0.y > 0.5f) ? s[j][1] * ATTN_SCALE : -1e9f;
            s[j][2] = (mk1.x > 0.5f) ? s[j][2] * ATTN_SCALE : -1e9f;
            s[j][3] = (mk1.y > 0.5f) ? s[j][3] * ATTN_SCALE : -1e9f;
            mx0 = fmaxf(mx0, fmaxf(s[j][0], s[j][1]));
            mx1 = fmaxf(mx1, fmaxf(s[j][2], s[j][3]));
        }
        mx0 = fmaxf(mx0, __shfl_xor_sync(0xffffffffu, mx0, 1));
        mx0 = fmaxf(mx0, __shfl_xor_sync(0xffffffffu, mx0, 2));
        mx1 = fmaxf(mx1, __shfl_xor_sync(0xffffffffu, mx1, 1));
        mx1 = fmaxf(mx1, __shfl_xor_sync(0xffffffffu, mx1, 2));

        float mn0 = fmaxf(m0r, mx0), mn1 = fmaxf(m1r, mx1);
        float al0 = __expf(m0r - mn0), al1 = __expf(m1r - mn1);
        m0r = mn0; m1r = mn1;

        float rs0 = 0.f, rs1 = 0.f;
#pragma unroll
        for (int j = 0; j < 8; j++) {
            float p0 = __expf(s[j][0] - mn0), p1 = __expf(s[j][1] - mn0);
            float p2 = __expf(s[j][2] - mn1), p3 = __expf(s[j][3] - mn1);
            rs0 += p0 + p1; rs1 += p2 + p3;
            int col = j * 8 + 2 * tg;
            Ps[mw + g][col] = p0;     Ps[mw + g][col + 1] = p1;
            Ps[mw + g + 8][col] = p2; Ps[mw + g + 8][col + 1] = p3;
        }
        rs0 += __shfl_xor_sync(0xffffffffu, rs0, 1);
        rs0 += __shfl_xor_sync(0xffffffffu, rs0, 2);
        rs1 += __shfl_xor_sync(0xffffffffu, rs1, 1);
        rs1 += __shfl_xor_sync(0xffffffffu, rs1, 2);
        l0 = l0 * al0 + rs0;
        l1 = l1 * al1 + rs1;
#pragma unroll
        for (int j = 0; j < 8; j++) {
            O[j][0] *= al0; O[j][1] *= al0; O[j][2] *= al1; O[j][3] *= al1;
        }
        __syncwarp();  // P tile (own warp rows) visible to all lanes

        // O += P @ V
#pragma unroll
        for (int k8 = 0; k8 < 8; k8++) {
            int kk = k8 * 8;
            unsigned a0 = f2tf(Ps[mw + g][kk + tg]);
            unsigned a1 = f2tf(Ps[mw + g + 8][kk + tg]);
            unsigned a2 = f2tf(Ps[mw + g][kk + tg + 4]);
            unsigned a3 = f2tf(Ps[mw + g + 8][kk + tg + 4]);
#pragma unroll
            for (int j = 0; j < 8; j++) {
                unsigned b0 = f2tf(Vs[kk + tg][j * 8 + g]);
                unsigned b1 = f2tf(Vs[kk + tg + 4][j * 8 + g]);
                mma_tf32(O[j], a0, a1, a2, a3, b0, b1);
            }
        }
    }

    float inv0 = 1.f / l0, inv1 = 1.f / l1;
    float* og = ctx + ((size_t)(b * NQ + q0)) * Dd + h * DH;
#pragma unroll
    for (int j = 0; j < 8; j++) {
        int col = j * 8 + 2 * tg;
        *(float2*)&og[(size_t)(mw + g) * Dd + col] = make_float2(O[j][0] * inv0, O[j][1] * inv0);
        *(float2*)&og[(size_t)(mw + g + 8) * Dd + col] = make_float2(O[j][2] * inv1, O[j][3] * inv1);
    }
}

// ---------------- scatter-add -------------------------------------------------
__global__ void k_scatter(const float* __restrict__ res, const int* __restrict__ qi,
                          float* __restrict__ upd, float* __restrict__ out) {
    int n = Bb * NQ * Dd;
    for (int i = blockIdx.x * blockDim.x + threadIdx.x; i < n; i += gridDim.x * blockDim.x) {
        int b = i / (NQ * Dd);
        int rem = i - b * (NQ * Dd);
        int q = rem >> 8;
        int d = rem & 255;
        int id = qi[q];
        float v = res[i];
        size_t o = ((size_t)b * NS + id) * Dd + d;
        atomicAdd(&upd[o], v);
        atomicAdd(&out[o], v);
    }
}

// ---------------- launch ------------------------------------------------------
extern "C" void kernel_launch(void* const* d_in, const int* in_sizes, int n_in,
                              void* d_out, int out_size) {
    const float* upd_in = (const float*)d_in[0];
    const float* emb    = (const float*)d_in[1];
    const float* mask   = (const float*)d_in[2];
    const float* Wq     = (const float*)d_in[3];
    const float* Wk     = (const float*)d_in[4];
    const float* Wv     = (const float*)d_in[5];
    const float* Wo     = (const float*)d_in[6];
    const float* W1     = (const float*)d_in[7];
    const float* b1     = (const float*)d_in[8];
    const float* W2     = (const float*)d_in[9];
    const float* b2     = (const float*)d_in[10];
    const float* sys_s  = (const float*)d_in[11];
    const float* sys_b  = (const float*)d_in[12];
    const float* eff_s  = (const float*)d_in[13];
    const float* eff_b  = (const float*)d_in[14];
    const float* in_s   = (const float*)d_in[15];
    const float* in_b   = (const float*)d_in[16];
    const float* out_s  = (const float*)d_in[17];
    const float* out_b  = (const float*)d_in[18];
    const int*   qidx   = (const int*)d_in[19];
    const int*   kidx   = (const int*)d_in[20];
    float* out = (float*)d_out;

    float *upd, *qb, *kb, *Qp, *Kp, *Vp, *ctx, *hb, *t1, *t2;
    cudaGetSymbolAddress((void**)&upd, g_upd);
    cudaGetSymbolAddress((void**)&qb,  g_q);
    cudaGetSymbolAddress((void**)&kb,  g_k);
    cudaGetSymbolAddress((void**)&Qp,  g_Qp);
    cudaGetSymbolAddress((void**)&Kp,  g_Kp);
    cudaGetSymbolAddress((void**)&Vp,  g_Vp);
    cudaGetSymbolAddress((void**)&ctx, g_ctx);
    cudaGetSymbolAddress((void**)&hb,  g_h);
    cudaGetSymbolAddress((void**)&t1,  g_t1);
    cudaGetSymbolAddress((void**)&t2,  g_t2);

    cudaFuncSetAttribute(flash_attn, cudaFuncAttributeMaxDynamicSharedMemorySize, 105472);

    int n_upd = Bb * NS * Dd;
    k_zero<<<8192, 256>>>(out, n_upd);
    k_copy<<<8192, 256>>>(upd_in, upd, n_upd);

    for (int l = 0; l < Ll; l++) {
        const float* mask_l = mask + (size_t)l * NQ * NK;
        const int* qi = qidx + l * NQ;
        const int* ki = kidx + l * NK;

        k_gather_ln<<<Bb * NQ, 256>>>(emb, upd, qi, sys_s, sys_b, qb, NQ);
        k_gather_ln<<<Bb * NK, 256>>>(emb, upd, ki, sys_s, sys_b, kb, NK);

        proj_mma<0><<<dim3(128, 4), 256>>>(qb, Wq, nullptr, Qp);
        proj_mma<0><<<dim3(256, 4), 256>>>(kb, Wk, nullptr, Kp);
        proj_mma<0><<<dim3(256, 4), 256>>>(kb, Wv, nullptr, Vp);

        flash_attn<<<dim3(NQ / 128, 1, Bb * Hh), 256, 105472>>>(Qp, Kp, Vp, mask_l, ctx);

        proj_mma<0><<<dim3(128, 4), 256>>>(ctx, Wo, nullptr, t1);
        k_ln<<<Bb * NQ, 256>>>(t1, in_s, in_b, hb);

        proj_mma<1><<<dim3(128, 4), 256>>>(hb, W1, b1, t1);
        proj_mma<0><<<dim3(128, 4), 256>>>(t1, W2, b2, t2);

        k_dln<<<Bb * NQ, 256>>>(hb, t2, out_s, out_b, eff_s, eff_b, ctx);
        k_scatter<<<8192, 256>>>(ctx, qi, upd, out);
    }
}